// round 4
// baseline (speedup 1.0000x reference)
#include <cuda_runtime.h>
#include <cstddef>

// ---------------- problem constants ----------------
#define BATCH 16
#define NPTS  1024              // N == M
#define DIM   64
#define L2E_EPS 144.2695040888963f       // log2(e) / eps, eps = 0.01
#define EPS_LN2 0.006931471805599453f    // eps * ln(2)
#define EPS_LOG_A (-0.06931461565651899f) // eps * log(1/1024 + 1e-8)  (== eps*log_b)

// ---------------- device state (no cudaMalloc allowed) ----------------
__device__ float    g_C[BATCH * NPTS * NPTS];   // 64 MB cost matrix
__device__ float    g_u[BATCH * NPTS];
__device__ float    g_v[BATCH * NPTS];
__device__ float    g_xn[BATCH * NPTS];
__device__ float    g_yn[BATCH * NPTS];
__device__ float    g_du[BATCH];
__device__ float    g_dv[BATCH];
__device__ int      g_done;
__device__ unsigned g_ticket;
__device__ float    g_part[2048];

// ---------------- helpers ----------------
__device__ __forceinline__ float ex2f(float x) {
    float y; asm("ex2.approx.ftz.f32 %0, %1;" : "=f"(y) : "f"(x)); return y;
}
__device__ __forceinline__ float lg2f(float x) {
    float y; asm("lg2.approx.f32 %0, %1;" : "=f"(y) : "f"(x)); return y;
}

// Branchless online log-sum-exp accumulate in log2 units.
// One MUFU per element: exp2(min-max) == exp2(-|w-m|); selects route it
// either as the rescale factor of s or as the new term.
__device__ __forceinline__ void lse_acc(float& m, float& s, float w) {
    float d  = w - m;
    float mn = fmaxf(m, w);
    float t  = ex2f(0.0f - fabsf(d));
    float a  = (d > 0.0f) ? t : 1.0f;
    float b  = (d > 0.0f) ? 1.0f : t;
    s = fmaf(s, a, b);
    m = mn;
}
__device__ __forceinline__ void lse_merge(float& m, float& s, float m2, float s2) {
    float M = fmaxf(m, m2);
    s = fmaf(s, ex2f(m - M), s2 * ex2f(m2 - M));
    m = M;
}

// ---------------- init: norms + state reset ----------------
// grid 4096 x 256: one warp per row of x then y (32768 rows total).
__global__ __launch_bounds__(256) void init_kernel(float* __restrict__ out,
                                                   const float* __restrict__ x,
                                                   const float* __restrict__ y) {
    int tid = threadIdx.x, w = tid >> 5, lane = tid & 31;
    int r = blockIdx.x * 8 + w;                 // 0 .. 32767
    bool is_x = (r < BATCH * NPTS);
    const float* src = is_x ? (x + (size_t)r * DIM)
                            : (y + (size_t)(r - BATCH * NPTS) * DIM);
    float a = src[lane], b = src[lane + 32];
    float sq = a * a + b * b;
    #pragma unroll
    for (int o = 16; o; o >>= 1) sq += __shfl_xor_sync(0xffffffffu, sq, o);
    if (lane == 0) {
        if (is_x) g_xn[r] = sq; else g_yn[r - BATCH * NPTS] = sq;
    }
    int g = blockIdx.x * 256 + tid;
    if (g < BATCH * NPTS) { g_u[g] = 0.0f; g_v[g] = 0.0f; }
    if (g < BATCH) { g_du[g] = 0.0f; g_dv[g] = 0.0f; out[g] = 0.0f; }
    if (g == 0) { g_done = 0; g_ticket = 0u; }
}

// ---------------- build C = |x|^2 + |y|^2 - 2 x.y ----------------
// grid (16,16,16), block 256: 64x64 output tile per CTA, 4x4 per thread.
__global__ __launch_bounds__(256) void c_kernel(const float* __restrict__ x,
                                                const float* __restrict__ y) {
    __shared__ float xs[64][65];
    __shared__ float ys[64][65];
    int tid = threadIdx.x;
    int b = blockIdx.z, i0 = blockIdx.y * 64, j0 = blockIdx.x * 64;
    const float* xb = x + ((size_t)(b * NPTS + i0)) * DIM;
    const float* yb = y + ((size_t)(b * NPTS + j0)) * DIM;
    #pragma unroll
    for (int t = 0; t < 4; t++) {
        int e = tid + t * 256;          // 0..1023
        int row = e >> 4, c4 = (e & 15) * 4;
        float4 vx = *(const float4*)(xb + row * DIM + c4);
        xs[row][c4] = vx.x; xs[row][c4 + 1] = vx.y; xs[row][c4 + 2] = vx.z; xs[row][c4 + 3] = vx.w;
        float4 vy = *(const float4*)(yb + row * DIM + c4);
        ys[row][c4] = vy.x; ys[row][c4 + 1] = vy.y; ys[row][c4 + 2] = vy.z; ys[row][c4 + 3] = vy.w;
    }
    __syncthreads();
    int tx = tid & 15, ty = tid >> 4;
    float acc[4][4];
    #pragma unroll
    for (int r = 0; r < 4; r++)
        #pragma unroll
        for (int c = 0; c < 4; c++) acc[r][c] = 0.0f;
    #pragma unroll 16
    for (int d = 0; d < 64; d++) {
        float a0 = xs[ty * 4 + 0][d], a1 = xs[ty * 4 + 1][d];
        float a2 = xs[ty * 4 + 2][d], a3 = xs[ty * 4 + 3][d];
        float b0 = ys[tx * 4 + 0][d], b1 = ys[tx * 4 + 1][d];
        float b2 = ys[tx * 4 + 2][d], b3 = ys[tx * 4 + 3][d];
        acc[0][0] = fmaf(a0, b0, acc[0][0]); acc[0][1] = fmaf(a0, b1, acc[0][1]);
        acc[0][2] = fmaf(a0, b2, acc[0][2]); acc[0][3] = fmaf(a0, b3, acc[0][3]);
        acc[1][0] = fmaf(a1, b0, acc[1][0]); acc[1][1] = fmaf(a1, b1, acc[1][1]);
        acc[1][2] = fmaf(a1, b2, acc[1][2]); acc[1][3] = fmaf(a1, b3, acc[1][3]);
        acc[2][0] = fmaf(a2, b0, acc[2][0]); acc[2][1] = fmaf(a2, b1, acc[2][1]);
        acc[2][2] = fmaf(a2, b2, acc[2][2]); acc[2][3] = fmaf(a2, b3, acc[2][3]);
        acc[3][0] = fmaf(a3, b0, acc[3][0]); acc[3][1] = fmaf(a3, b1, acc[3][1]);
        acc[3][2] = fmaf(a3, b2, acc[3][2]); acc[3][3] = fmaf(a3, b3, acc[3][3]);
    }
    float* Cb = g_C + ((size_t)b << 20);
    float yn0 = g_yn[b * NPTS + j0 + tx * 4 + 0];
    float yn1 = g_yn[b * NPTS + j0 + tx * 4 + 1];
    float yn2 = g_yn[b * NPTS + j0 + tx * 4 + 2];
    float yn3 = g_yn[b * NPTS + j0 + tx * 4 + 3];
    #pragma unroll
    for (int r = 0; r < 4; r++) {
        int i = i0 + ty * 4 + r;
        float xni = g_xn[b * NPTS + i];
        float4 o;
        o.x = xni + yn0 - 2.0f * acc[r][0];
        o.y = xni + yn1 - 2.0f * acc[r][1];
        o.z = xni + yn2 - 2.0f * acc[r][2];
        o.w = xni + yn3 - 2.0f * acc[r][3];
        *(float4*)(Cb + (size_t)i * NPTS + j0 + tx * 4) = o;
    }
}

// ---------------- row update: u_i = eps(log_a - LSE_j((v_j - C_ij)/eps)) ----------------
// grid 2048 x 256: one warp per row, 8 rows/CTA (all in same batch).
__global__ __launch_bounds__(256) void row_kernel() {
    if (g_done) return;
    __shared__ float sh_vL[NPTS];
    __shared__ float sh_du[8];
    int tid = threadIdx.x, w = tid >> 5, lane = tid & 31;
    int row = blockIdx.x * 8 + w;
    int b = row >> 10;
    const float* vb = g_v + (b << 10);
    for (int t = tid; t < NPTS; t += 256) sh_vL[t] = vb[t] * L2E_EPS;
    __syncthreads();
    const float* Crow = g_C + ((size_t)row << 10);
    float m = -1e30f, s = 0.0f;
    #pragma unroll
    for (int k = 0; k < 8; k++) {
        int j = k * 128 + lane * 4;
        float4 c  = *(const float4*)(Crow + j);
        float4 vl = *(const float4*)(sh_vL + j);
        lse_acc(m, s, fmaf(c.x, -L2E_EPS, vl.x));
        lse_acc(m, s, fmaf(c.y, -L2E_EPS, vl.y));
        lse_acc(m, s, fmaf(c.z, -L2E_EPS, vl.z));
        lse_acc(m, s, fmaf(c.w, -L2E_EPS, vl.w));
    }
    #pragma unroll
    for (int o = 16; o; o >>= 1) {
        float m2 = __shfl_xor_sync(0xffffffffu, m, o);
        float s2 = __shfl_xor_sync(0xffffffffu, s, o);
        lse_merge(m, s, m2, s2);
    }
    if (lane == 0) {
        float u_new = EPS_LOG_A - EPS_LN2 * (m + lg2f(s));
        float u_old = g_u[row];
        g_u[row] = u_new;
        sh_du[w] = fabsf(u_new - u_old);
    }
    __syncthreads();
    if (tid == 0) {
        float a = 0.0f;
        #pragma unroll
        for (int i = 0; i < 8; i++) a += sh_du[i];
        atomicAdd(&g_du[b], a);
    }
}

// ---------------- col update: v_j = eps(log_b - LSE_i((u_i - C_ij)/eps)) ----------------
// grid 512 x 256: CTA = 32 columns x 8 row-groups of 128 rows. Coalesced LDG.32.
// Last CTA (ticket) folds the early-stop decision.
__global__ __launch_bounds__(256) void col_kernel() {
    if (g_done) return;
    __shared__ float sh_uL[NPTS];
    __shared__ float sh_m[256];
    __shared__ float sh_s[256];
    int tid = threadIdx.x;
    int b  = blockIdx.x >> 5;            // 32 col-blocks per batch
    int j0 = (blockIdx.x & 31) * 32;
    const float* ub = g_u + (b << 10);
    for (int t = tid; t < NPTS; t += 256) sh_uL[t] = ub[t] * L2E_EPS;
    __syncthreads();
    int c = tid & 31;                    // column within block
    int g = tid >> 5;                    // row group
    int ibase = g * 128;
    const float* Cp = g_C + (((size_t)(b << 10) + ibase) << 10) + (j0 + c);
    float m = -1e30f, s = 0.0f;
    #pragma unroll 4
    for (int r = 0; r < 128; r++) {
        float cv = Cp[(size_t)r << 10];
        lse_acc(m, s, fmaf(cv, -L2E_EPS, sh_uL[ibase + r]));
    }
    sh_m[tid] = m; sh_s[tid] = s;
    __syncthreads();
    if (tid < 32) {
        float M = sh_m[tid], S = sh_s[tid];
        #pragma unroll
        for (int gg = 1; gg < 8; gg++) lse_merge(M, S, sh_m[gg * 32 + tid], sh_s[gg * 32 + tid]);
        float v_new = EPS_LOG_A - EPS_LN2 * (M + lg2f(S));
        int vidx = (b << 10) + j0 + tid;
        float v_old = g_v[vidx];
        g_v[vidx] = v_new;
        float dv = fabsf(v_new - v_old);
        #pragma unroll
        for (int o = 16; o; o >>= 1) dv += __shfl_xor_sync(0xffffffffu, dv, o);
        if (tid == 0) {
            atomicAdd(&g_dv[b], dv);
            __threadfence();
            unsigned t = atomicAdd(&g_ticket, 1u);
            if (t == gridDim.x - 1) {   // last CTA: finalize early-stop decision
                float diff = 0.0f;
                for (int bb = 0; bb < BATCH; bb++) {
                    diff += g_du[bb] + g_dv[bb];
                    g_du[bb] = 0.0f; g_dv[bb] = 0.0f;
                }
                diff *= (1.0f / BATCH);
                if (diff < 1e-4f) g_done = 1;
                g_ticket = 0u;
            }
        }
    }
}

// ---------------- final cost: cost[b] = sum_ij exp((u+v-C)/eps) * C ----------------
__global__ __launch_bounds__(256) void cost_kernel() {
    __shared__ float sh_vL[NPTS];
    __shared__ float sh_acc[8];
    int tid = threadIdx.x, w = tid >> 5, lane = tid & 31;
    int row = blockIdx.x * 8 + w;
    int b = row >> 10;
    const float* vb = g_v + (b << 10);
    for (int t = tid; t < NPTS; t += 256) sh_vL[t] = vb[t] * L2E_EPS;
    __syncthreads();
    float uL = g_u[row] * L2E_EPS;
    const float* Crow = g_C + ((size_t)row << 10);
    float acc = 0.0f;
    #pragma unroll
    for (int k = 0; k < 8; k++) {
        int j = k * 128 + lane * 4;
        float4 c  = *(const float4*)(Crow + j);
        float4 vl = *(const float4*)(sh_vL + j);
        float p;
        p = ex2f(fmaf(c.x, -L2E_EPS, uL + vl.x)); acc = fmaf(p, c.x, acc);
        p = ex2f(fmaf(c.y, -L2E_EPS, uL + vl.y)); acc = fmaf(p, c.y, acc);
        p = ex2f(fmaf(c.z, -L2E_EPS, uL + vl.z)); acc = fmaf(p, c.z, acc);
        p = ex2f(fmaf(c.w, -L2E_EPS, uL + vl.w)); acc = fmaf(p, c.w, acc);
    }
    #pragma unroll
    for (int o = 16; o; o >>= 1) acc += __shfl_xor_sync(0xffffffffu, acc, o);
    if (lane == 0) sh_acc[w] = acc;
    __syncthreads();
    if (tid == 0) {
        float t = 0.0f;
        #pragma unroll
        for (int i = 0; i < 8; i++) t += sh_acc[i];
        g_part[blockIdx.x] = t;      // 128 partials per batch, deterministic order
    }
}

__global__ __launch_bounds__(256) void cost_final(float* __restrict__ out) {
    int tid = threadIdx.x;           // 256 threads: 16 per batch
    int b = tid >> 4, idx = tid & 15;
    float s = 0.0f;
    #pragma unroll
    for (int k = 0; k < 8; k++) s += g_part[b * 128 + idx * 8 + k];
    #pragma unroll
    for (int o = 8; o; o >>= 1) s += __shfl_xor_sync(0xffffffffu, s, o);
    if (idx == 0) out[b] = s;
}

// ---------------- launch ----------------
extern "C" void kernel_launch(void* const* d_in, const int* in_sizes, int n_in,
                              void* d_out, int out_size) {
    (void)in_sizes; (void)n_in; (void)out_size;
    const float* x = (const float*)d_in[0];
    const float* y = (const float*)d_in[1];
    float* out = (float*)d_out;

    init_kernel<<<4096, 256>>>(out, x, y);
    c_kernel<<<dim3(16, 16, 16), 256>>>(x, y);
    for (int it = 0; it < 100; ++it) {
        row_kernel<<<2048, 256>>>();
        col_kernel<<<512, 256>>>();
    }
    cost_kernel<<<2048, 256>>>();
    cost_final<<<1, 256>>>(out);
}

// round 5
// speedup vs baseline: 1.0522x; 1.0522x over previous
#include <cuda_runtime.h>
#include <cstddef>

// ---------------- problem constants ----------------
#define BATCH 16
#define NPTS  1024              // N == M
#define DIM   64
#define L2E_EPS 144.2695040888963f       // log2(e) / eps, eps = 0.01
#define EPS_LN2 0.006931471805599453f    // eps * ln(2)
#define EPS_LOG_A (-0.06931461565651899f) // eps * log(1/1024 + 1e-8)  (== eps*log_b)

#define NSLAB 4                 // row slabs in col pass
#define NGRP  (BATCH * 32)      // column groups (32 cols each) = 512

// ---------------- device state (no cudaMalloc allowed) ----------------
__device__ float    g_C[BATCH * NPTS * NPTS];   // 64 MB cost matrix
__device__ float    g_u[BATCH * NPTS];
__device__ float    g_v[BATCH * NPTS];
__device__ float    g_xn[BATCH * NPTS];
__device__ float    g_yn[BATCH * NPTS];
__device__ float    g_du[BATCH];
__device__ float    g_dv[BATCH];
__device__ int      g_done;
__device__ unsigned g_ticket;
__device__ unsigned g_gtick[NGRP];
__device__ float2   g_cpart[NGRP * NSLAB * 32]; // per (group, slab, col) LSE partial
__device__ float    g_part[2048];

// ---------------- helpers ----------------
__device__ __forceinline__ float ex2f(float x) {
    float y; asm("ex2.approx.ftz.f32 %0, %1;" : "=f"(y) : "f"(x)); return y;
}
__device__ __forceinline__ float lg2f(float x) {
    float y; asm("lg2.approx.f32 %0, %1;" : "=f"(y) : "f"(x)); return y;
}

// Branchless online log-sum-exp accumulate in log2 units (one MUFU/elt).
__device__ __forceinline__ void lse_acc(float& m, float& s, float w) {
    float d  = w - m;
    float mn = fmaxf(m, w);
    float t  = ex2f(0.0f - fabsf(d));
    float a  = (d > 0.0f) ? t : 1.0f;
    float b  = (d > 0.0f) ? 1.0f : t;
    s = fmaf(s, a, b);
    m = mn;
}
__device__ __forceinline__ void lse_merge(float& m, float& s, float m2, float s2) {
    float M = fmaxf(m, m2);
    s = fmaf(s, ex2f(m - M), s2 * ex2f(m2 - M));
    m = M;
}

// ---------------- init: norms + state reset ----------------
__global__ __launch_bounds__(256) void init_kernel(float* __restrict__ out,
                                                   const float* __restrict__ x,
                                                   const float* __restrict__ y) {
    int tid = threadIdx.x, w = tid >> 5, lane = tid & 31;
    int r = blockIdx.x * 8 + w;                 // 0 .. 32767
    bool is_x = (r < BATCH * NPTS);
    const float* src = is_x ? (x + (size_t)r * DIM)
                            : (y + (size_t)(r - BATCH * NPTS) * DIM);
    float a = src[lane], b = src[lane + 32];
    float sq = a * a + b * b;
    #pragma unroll
    for (int o = 16; o; o >>= 1) sq += __shfl_xor_sync(0xffffffffu, sq, o);
    if (lane == 0) {
        if (is_x) g_xn[r] = sq; else g_yn[r - BATCH * NPTS] = sq;
    }
    int g = blockIdx.x * 256 + tid;
    if (g < BATCH * NPTS) { g_u[g] = 0.0f; g_v[g] = 0.0f; }
    if (g < BATCH) { g_du[g] = 0.0f; g_dv[g] = 0.0f; out[g] = 0.0f; }
    if (g < NGRP) g_gtick[g] = 0u;
    if (g == 0) { g_done = 0; g_ticket = 0u; }
}

// ---------------- build C = |x|^2 + |y|^2 - 2 x.y ----------------
__global__ __launch_bounds__(256) void c_kernel(const float* __restrict__ x,
                                                const float* __restrict__ y) {
    __shared__ float xs[64][65];
    __shared__ float ys[64][65];
    int tid = threadIdx.x;
    int b = blockIdx.z, i0 = blockIdx.y * 64, j0 = blockIdx.x * 64;
    const float* xb = x + ((size_t)(b * NPTS + i0)) * DIM;
    const float* yb = y + ((size_t)(b * NPTS + j0)) * DIM;
    #pragma unroll
    for (int t = 0; t < 4; t++) {
        int e = tid + t * 256;
        int row = e >> 4, c4 = (e & 15) * 4;
        float4 vx = *(const float4*)(xb + row * DIM + c4);
        xs[row][c4] = vx.x; xs[row][c4 + 1] = vx.y; xs[row][c4 + 2] = vx.z; xs[row][c4 + 3] = vx.w;
        float4 vy = *(const float4*)(yb + row * DIM + c4);
        ys[row][c4] = vy.x; ys[row][c4 + 1] = vy.y; ys[row][c4 + 2] = vy.z; ys[row][c4 + 3] = vy.w;
    }
    __syncthreads();
    int tx = tid & 15, ty = tid >> 4;
    float acc[4][4];
    #pragma unroll
    for (int r = 0; r < 4; r++)
        #pragma unroll
        for (int c = 0; c < 4; c++) acc[r][c] = 0.0f;
    #pragma unroll 16
    for (int d = 0; d < 64; d++) {
        float a0 = xs[ty * 4 + 0][d], a1 = xs[ty * 4 + 1][d];
        float a2 = xs[ty * 4 + 2][d], a3 = xs[ty * 4 + 3][d];
        float b0 = ys[tx * 4 + 0][d], b1 = ys[tx * 4 + 1][d];
        float b2 = ys[tx * 4 + 2][d], b3 = ys[tx * 4 + 3][d];
        acc[0][0] = fmaf(a0, b0, acc[0][0]); acc[0][1] = fmaf(a0, b1, acc[0][1]);
        acc[0][2] = fmaf(a0, b2, acc[0][2]); acc[0][3] = fmaf(a0, b3, acc[0][3]);
        acc[1][0] = fmaf(a1, b0, acc[1][0]); acc[1][1] = fmaf(a1, b1, acc[1][1]);
        acc[1][2] = fmaf(a1, b2, acc[1][2]); acc[1][3] = fmaf(a1, b3, acc[1][3]);
        acc[2][0] = fmaf(a2, b0, acc[2][0]); acc[2][1] = fmaf(a2, b1, acc[2][1]);
        acc[2][2] = fmaf(a2, b2, acc[2][2]); acc[2][3] = fmaf(a2, b3, acc[2][3]);
        acc[3][0] = fmaf(a3, b0, acc[3][0]); acc[3][1] = fmaf(a3, b1, acc[3][1]);
        acc[3][2] = fmaf(a3, b2, acc[3][2]); acc[3][3] = fmaf(a3, b3, acc[3][3]);
    }
    float* Cb = g_C + ((size_t)b << 20);
    float yn0 = g_yn[b * NPTS + j0 + tx * 4 + 0];
    float yn1 = g_yn[b * NPTS + j0 + tx * 4 + 1];
    float yn2 = g_yn[b * NPTS + j0 + tx * 4 + 2];
    float yn3 = g_yn[b * NPTS + j0 + tx * 4 + 3];
    #pragma unroll
    for (int r = 0; r < 4; r++) {
        int i = i0 + ty * 4 + r;
        float xni = g_xn[b * NPTS + i];
        float4 o;
        o.x = xni + yn0 - 2.0f * acc[r][0];
        o.y = xni + yn1 - 2.0f * acc[r][1];
        o.z = xni + yn2 - 2.0f * acc[r][2];
        o.w = xni + yn3 - 2.0f * acc[r][3];
        *(float4*)(Cb + (size_t)i * NPTS + j0 + tx * 4) = o;
    }
}

// ---------------- row update: u_i = eps(log_a - LSE_j((v_j - C_ij)/eps)) ----------------
// grid 2048 x 256: one warp per row. Register two-phase LSE (exact block max,
// then independent ex2 sums) in two 16-element halves -> no MUFU in the chain.
__global__ __launch_bounds__(256) void row_kernel() {
    if (g_done) return;
    __shared__ float sh_vL[NPTS];
    __shared__ float sh_du[8];
    int tid = threadIdx.x, w = tid >> 5, lane = tid & 31;
    int row = blockIdx.x * 8 + w;
    int b = row >> 10;
    const float* vb = g_v + (b << 10);
    for (int t = tid; t < NPTS; t += 256) sh_vL[t] = vb[t] * L2E_EPS;
    __syncthreads();
    const float* Crow = g_C + ((size_t)row << 10);

    float m = -1e30f, s = 0.0f;
    #pragma unroll
    for (int h = 0; h < 2; h++) {
        float wv[16];
        #pragma unroll
        for (int k = 0; k < 4; k++) {
            int j = (h * 4 + k) * 128 + lane * 4;
            float4 c  = *(const float4*)(Crow + j);
            float4 vl = *(const float4*)(sh_vL + j);
            wv[k * 4 + 0] = fmaf(c.x, -L2E_EPS, vl.x);
            wv[k * 4 + 1] = fmaf(c.y, -L2E_EPS, vl.y);
            wv[k * 4 + 2] = fmaf(c.z, -L2E_EPS, vl.z);
            wv[k * 4 + 3] = fmaf(c.w, -L2E_EPS, vl.w);
        }
        // exact max over 16 (pipelined tree)
        float t0 = fmaxf(wv[0], wv[1]),   t1 = fmaxf(wv[2], wv[3]);
        float t2 = fmaxf(wv[4], wv[5]),   t3 = fmaxf(wv[6], wv[7]);
        float t4 = fmaxf(wv[8], wv[9]),   t5 = fmaxf(wv[10], wv[11]);
        float t6 = fmaxf(wv[12], wv[13]), t7 = fmaxf(wv[14], wv[15]);
        t0 = fmaxf(t0, t1); t2 = fmaxf(t2, t3); t4 = fmaxf(t4, t5); t6 = fmaxf(t6, t7);
        float bm = fmaxf(fmaxf(t0, t2), fmaxf(t4, t6));
        // independent ex2 sums, 4 chains
        float s0 = ex2f(wv[0] - bm)  + ex2f(wv[4] - bm);
        float s1 = ex2f(wv[1] - bm)  + ex2f(wv[5] - bm);
        float s2 = ex2f(wv[2] - bm)  + ex2f(wv[6] - bm);
        float s3 = ex2f(wv[3] - bm)  + ex2f(wv[7] - bm);
        s0 += ex2f(wv[8] - bm)  + ex2f(wv[12] - bm);
        s1 += ex2f(wv[9] - bm)  + ex2f(wv[13] - bm);
        s2 += ex2f(wv[10] - bm) + ex2f(wv[14] - bm);
        s3 += ex2f(wv[11] - bm) + ex2f(wv[15] - bm);
        float bs = (s0 + s1) + (s2 + s3);
        lse_merge(m, s, bm, bs);
    }
    #pragma unroll
    for (int o = 16; o; o >>= 1) {
        float m2 = __shfl_xor_sync(0xffffffffu, m, o);
        float s2 = __shfl_xor_sync(0xffffffffu, s, o);
        lse_merge(m, s, m2, s2);
    }
    if (lane == 0) {
        float u_new = EPS_LOG_A - EPS_LN2 * (m + lg2f(s));
        float u_old = g_u[row];
        g_u[row] = u_new;
        sh_du[w] = fabsf(u_new - u_old);
    }
    __syncthreads();
    if (tid == 0) {
        float a = 0.0f;
        #pragma unroll
        for (int i = 0; i < 8; i++) a += sh_du[i];
        atomicAdd(&g_du[b], a);
    }
}

// ---------------- col update: v_j = eps(log_b - LSE_i((u_i - C_ij)/eps)) ----------------
// grid 2048 x 256: CTA = (batch, colgroup of 32 cols, row slab of 256 rows).
// Each warp covers 32 rows per column; slab partials merged by the last CTA
// of each column group (ticket), which also folds the early-stop decision.
__global__ __launch_bounds__(256) void col_kernel() {
    if (g_done) return;
    __shared__ float sh_uL[256];
    __shared__ float sh_m[256];
    __shared__ float sh_s[256];
    __shared__ unsigned sh_last;
    int tid  = threadIdx.x;
    int grp  = blockIdx.x >> 2;            // 0 .. 511 : (b, colgroup)
    int slab = blockIdx.x & 3;
    int b    = grp >> 5;
    int j0   = (grp & 31) * 32;
    int r0   = slab * 256;
    const float* ub = g_u + (b << 10) + r0;
    for (int t = tid; t < 256; t += 256) sh_uL[t] = ub[t] * L2E_EPS;
    __syncthreads();
    int c = tid & 31;
    int g = tid >> 5;                      // 8 row groups of 32 rows
    const float* Cp = g_C + (((size_t)(b << 10) + r0 + g * 32) << 10) + (j0 + c);
    float m = -1e30f, s = 0.0f;
    #pragma unroll 8
    for (int r = 0; r < 32; r++) {
        float cv = __ldg(Cp + ((size_t)r << 10));
        lse_acc(m, s, fmaf(cv, -L2E_EPS, sh_uL[g * 32 + r]));
    }
    sh_m[tid] = m; sh_s[tid] = s;
    __syncthreads();
    if (tid < 32) {
        float M = sh_m[tid], S = sh_s[tid];
        #pragma unroll
        for (int gg = 1; gg < 8; gg++) lse_merge(M, S, sh_m[gg * 32 + tid], sh_s[gg * 32 + tid]);
        g_cpart[(grp * NSLAB + slab) * 32 + tid] = make_float2(M, S);
    }
    __syncthreads();
    if (tid == 0) {
        __threadfence();
        sh_last = atomicAdd(&g_gtick[grp], 1u);
    }
    __syncthreads();
    if (sh_last != NSLAB - 1) return;      // not the last slab CTA of this group

    // ---- merge the NSLAB partials for these 32 columns ----
    if (tid < 32) {
        const float2* P = g_cpart + (size_t)grp * NSLAB * 32;
        float2 p0 = __ldcg(&P[0 * 32 + tid]);
        float2 p1 = __ldcg(&P[1 * 32 + tid]);
        float2 p2 = __ldcg(&P[2 * 32 + tid]);
        float2 p3 = __ldcg(&P[3 * 32 + tid]);
        float M = p0.x, S = p0.y;
        lse_merge(M, S, p1.x, p1.y);
        lse_merge(M, S, p2.x, p2.y);
        lse_merge(M, S, p3.x, p3.y);
        float v_new = EPS_LOG_A - EPS_LN2 * (M + lg2f(S));
        int vidx = (b << 10) + j0 + tid;
        float v_old = g_v[vidx];
        g_v[vidx] = v_new;
        float dv = fabsf(v_new - v_old);
        #pragma unroll
        for (int o = 16; o; o >>= 1) dv += __shfl_xor_sync(0xffffffffu, dv, o);
        if (tid == 0) {
            g_gtick[grp] = 0u;             // reset for next launch
            atomicAdd(&g_dv[b], dv);
            __threadfence();
            unsigned t = atomicAdd(&g_ticket, 1u);
            if (t == NGRP - 1) {           // last group: early-stop decision
                float diff = 0.0f;
                for (int bb = 0; bb < BATCH; bb++) {
                    diff += g_du[bb] + g_dv[bb];
                    g_du[bb] = 0.0f; g_dv[bb] = 0.0f;
                }
                diff *= (1.0f / BATCH);
                if (diff < 1e-4f) g_done = 1;
                g_ticket = 0u;
            }
        }
    }
}

// ---------------- final cost: cost[b] = sum_ij exp((u+v-C)/eps) * C ----------------
__global__ __launch_bounds__(256) void cost_kernel() {
    __shared__ float sh_vL[NPTS];
    __shared__ float sh_acc[8];
    int tid = threadIdx.x, w = tid >> 5, lane = tid & 31;
    int row = blockIdx.x * 8 + w;
    int b = row >> 10;
    const float* vb = g_v + (b << 10);
    for (int t = tid; t < NPTS; t += 256) sh_vL[t] = vb[t] * L2E_EPS;
    __syncthreads();
    float uL = g_u[row] * L2E_EPS;
    const float* Crow = g_C + ((size_t)row << 10);
    float acc = 0.0f;
    #pragma unroll
    for (int k = 0; k < 8; k++) {
        int j = k * 128 + lane * 4;
        float4 c  = *(const float4*)(Crow + j);
        float4 vl = *(const float4*)(sh_vL + j);
        float p;
        p = ex2f(fmaf(c.x, -L2E_EPS, uL + vl.x)); acc = fmaf(p, c.x, acc);
        p = ex2f(fmaf(c.y, -L2E_EPS, uL + vl.y)); acc = fmaf(p, c.y, acc);
        p = ex2f(fmaf(c.z, -L2E_EPS, uL + vl.z)); acc = fmaf(p, c.z, acc);
        p = ex2f(fmaf(c.w, -L2E_EPS, uL + vl.w)); acc = fmaf(p, c.w, acc);
    }
    #pragma unroll
    for (int o = 16; o; o >>= 1) acc += __shfl_xor_sync(0xffffffffu, acc, o);
    if (lane == 0) sh_acc[w] = acc;
    __syncthreads();
    if (tid == 0) {
        float t = 0.0f;
        #pragma unroll
        for (int i = 0; i < 8; i++) t += sh_acc[i];
        g_part[blockIdx.x] = t;
    }
}

__global__ __launch_bounds__(256) void cost_final(float* __restrict__ out) {
    int tid = threadIdx.x;
    int b = tid >> 4, idx = tid & 15;
    float s = 0.0f;
    #pragma unroll
    for (int k = 0; k < 8; k++) s += g_part[b * 128 + idx * 8 + k];
    #pragma unroll
    for (int o = 8; o; o >>= 1) s += __shfl_xor_sync(0xffffffffu, s, o);
    if (idx == 0) out[b] = s;
}

// ---------------- launch ----------------
extern "C" void kernel_launch(void* const* d_in, const int* in_sizes, int n_in,
                              void* d_out, int out_size) {
    (void)in_sizes; (void)n_in; (void)out_size;
    const float* x = (const float*)d_in[0];
    const float* y = (const float*)d_in[1];
    float* out = (float*)d_out;

    init_kernel<<<4096, 256>>>(out, x, y);
    c_kernel<<<dim3(16, 16, 16), 256>>>(x, y);
    for (int it = 0; it < 100; ++it) {
        row_kernel<<<2048, 256>>>();
        col_kernel<<<2048, 256>>>();
    }
    cost_kernel<<<2048, 256>>>();
    cost_final<<<1, 256>>>(out);
}